// round 1
// baseline (speedup 1.0000x reference)
#include <cuda_runtime.h>
#include <math.h>

#define HID   2048
#define NH    16
#define HD    128
#define BATCH 4
#define SEQ   2048
#define MROWS (BATCH*SEQ)     // 8192
#define QKVN  (3*HID)         // 6144

// Scratch (allocation-guard-safe __device__ globals)
__device__ float g_qkv[(size_t)MROWS * QKVN];   // [8192, 6144]
__device__ float g_attn[(size_t)MROWS * HID];   // [8192, 2048]

// ---------------------------------------------------------------------------
// SGEMM: C[M,N] = A[M,K] @ B[N,K]^T + bias[N]
// 128x128 block tile, K-step 8, 256 threads, 8x8 micro-tile per thread.
// M, N, K all multiples of 128/8 here, so no bounds checks.
// ---------------------------------------------------------------------------
__global__ __launch_bounds__(256)
void sgemm_bias_kernel(const float* __restrict__ A,
                       const float* __restrict__ B,
                       const float* __restrict__ bias,
                       float* __restrict__ C,
                       int N, int K)
{
    __shared__ float As[8][128];
    __shared__ float Bs[8][128];

    const int tid = threadIdx.x;
    const int lr  = tid >> 1;          // 0..127 (tile row for gmem load)
    const int lc  = (tid & 1) << 2;    // 0 or 4 (k offset for gmem load)
    const int ty  = tid >> 4;          // 0..15
    const int tx  = tid & 15;          // 0..15

    const float* Ab = A + (size_t)blockIdx.y * 128 * K;
    const float* Bb = B + (size_t)blockIdx.x * 128 * K;

    float acc[8][8];
#pragma unroll
    for (int i = 0; i < 8; ++i)
#pragma unroll
        for (int j = 0; j < 8; ++j) acc[i][j] = 0.f;

    for (int k0 = 0; k0 < K; k0 += 8) {
        float4 a = *(const float4*)(Ab + (size_t)lr * K + k0 + lc);
        float4 b = *(const float4*)(Bb + (size_t)lr * K + k0 + lc);
        __syncthreads();   // previous compute done before overwriting smem
        As[lc + 0][lr] = a.x; As[lc + 1][lr] = a.y;
        As[lc + 2][lr] = a.z; As[lc + 3][lr] = a.w;
        Bs[lc + 0][lr] = b.x; Bs[lc + 1][lr] = b.y;
        Bs[lc + 2][lr] = b.z; Bs[lc + 3][lr] = b.w;
        __syncthreads();

#pragma unroll
        for (int k = 0; k < 8; ++k) {
            float ar[8], br[8];
            *(float4*)(ar)     = *(const float4*)(&As[k][ty * 8]);
            *(float4*)(ar + 4) = *(const float4*)(&As[k][ty * 8 + 4]);
            *(float4*)(br)     = *(const float4*)(&Bs[k][tx * 8]);
            *(float4*)(br + 4) = *(const float4*)(&Bs[k][tx * 8 + 4]);
#pragma unroll
            for (int i = 0; i < 8; ++i)
#pragma unroll
                for (int j = 0; j < 8; ++j)
                    acc[i][j] = fmaf(ar[i], br[j], acc[i][j]);
        }
    }

    const int row0 = blockIdx.y * 128 + ty * 8;
    const int col0 = blockIdx.x * 128 + tx * 8;
    float bv[8];
#pragma unroll
    for (int j = 0; j < 8; ++j) bv[j] = bias[col0 + j];
#pragma unroll
    for (int i = 0; i < 8; ++i) {
        float4 o0 = make_float4(acc[i][0] + bv[0], acc[i][1] + bv[1],
                                acc[i][2] + bv[2], acc[i][3] + bv[3]);
        float4 o1 = make_float4(acc[i][4] + bv[4], acc[i][5] + bv[5],
                                acc[i][6] + bv[6], acc[i][7] + bv[7]);
        *(float4*)(C + (size_t)(row0 + i) * N + col0)     = o0;
        *(float4*)(C + (size_t)(row0 + i) * N + col0 + 4) = o1;
    }
}

// ---------------------------------------------------------------------------
// Flash attention (fp32, online softmax, causal), Bq=Bk=64, D=128.
// Grid: (SEQ/64, NH, BATCH), 256 threads.
// qkv layout row r = b*SEQ+s, cols: [0,2048)=Q, [2048,4096)=K, [4096,6144)=V,
// within each: h*128 + d.
// ---------------------------------------------------------------------------
__global__ __launch_bounds__(256)
void flash_attn_kernel(const float* __restrict__ qkv,
                       float* __restrict__ attn)
{
    extern __shared__ float sm[];
    float* Qs   = sm;                 // 64*128
    float* Ks   = Qs + 64 * 128;      // 64*128
    float* Vs   = Ks + 64 * 128;      // 64*128
    float* Ss   = Vs + 64 * 128;      // 64*65 (padded)
    float* mrow = Ss + 64 * 65;       // 64
    float* lrow = mrow + 64;          // 64
    float* crow = lrow + 64;          // 64

    const int qt  = blockIdx.x;
    const int h   = blockIdx.y;
    const int b   = blockIdx.z;
    const int tid = threadIdx.x;
    const int ty  = tid >> 4, tx = tid & 15;
    const int r0  = ty << 2;     // 4 rows per thread (S and O share rows)
    const int cs  = tx << 2;     // 4 S cols per thread
    const int co  = tx << 3;     // 8 O cols per thread
    const int q0  = qt * 64;
    const float scale = 0.08838834764831845f;  // 1/sqrt(128)

    const float* base = qkv + (size_t)b * SEQ * QKVN;

    // Load Q tile (64x128)
    for (int i = tid; i < 64 * 32; i += 256) {
        int r = i >> 5, c4 = (i & 31) << 2;
        *(float4*)(Qs + r * 128 + c4) =
            *(const float4*)(base + (size_t)(q0 + r) * QKVN + h * HD + c4);
    }
    if (tid < 64) { mrow[tid] = -INFINITY; lrow[tid] = 0.f; }

    float acc[4][8];
#pragma unroll
    for (int i = 0; i < 4; ++i)
#pragma unroll
        for (int j = 0; j < 8; ++j) acc[i][j] = 0.f;

    for (int kt = 0; kt <= qt; ++kt) {
        const int k0 = kt * 64;
        __syncthreads();  // Q visible (1st iter) / prev PV done reading K,V
        for (int i = tid; i < 64 * 32; i += 256) {
            int r = i >> 5, c4 = (i & 31) << 2;
            const float* p = base + (size_t)(k0 + r) * QKVN + HID + h * HD + c4;
            *(float4*)(Ks + r * 128 + c4) = *(const float4*)(p);
            *(float4*)(Vs + r * 128 + c4) = *(const float4*)(p + HID);
        }
        __syncthreads();

        // S = Q K^T (4x4 per thread)
        float s[4][4];
#pragma unroll
        for (int i = 0; i < 4; ++i)
#pragma unroll
            for (int j = 0; j < 4; ++j) s[i][j] = 0.f;

        for (int d = 0; d < 128; d += 4) {
            float4 qv[4], kv[4];
#pragma unroll
            for (int i = 0; i < 4; ++i)
                qv[i] = *(const float4*)(Qs + (r0 + i) * 128 + d);
#pragma unroll
            for (int j = 0; j < 4; ++j)
                kv[j] = *(const float4*)(Ks + (cs + j) * 128 + d);
#pragma unroll
            for (int i = 0; i < 4; ++i)
#pragma unroll
                for (int j = 0; j < 4; ++j)
                    s[i][j] += qv[i].x * kv[j].x + qv[i].y * kv[j].y
                             + qv[i].z * kv[j].z + qv[i].w * kv[j].w;
        }
#pragma unroll
        for (int i = 0; i < 4; ++i)
#pragma unroll
            for (int j = 0; j < 4; ++j) {
                int qg = q0 + r0 + i, kg = k0 + cs + j;
                Ss[(r0 + i) * 65 + cs + j] =
                    (kg <= qg) ? s[i][j] * scale : -INFINITY;
            }
        __syncthreads();

        // Online softmax (one row per thread, 64 rows)
        if (tid < 64) {
            const int r = tid;
            float mold = mrow[r];
            float mx = mold;
            for (int c = 0; c < 64; ++c) mx = fmaxf(mx, Ss[r * 65 + c]);
            float corr = __expf(mold - mx);
            float sum = 0.f;
            for (int c = 0; c < 64; ++c) {
                float p = __expf(Ss[r * 65 + c] - mx);
                Ss[r * 65 + c] = p;
                sum += p;
            }
            mrow[r] = mx;
            lrow[r] = lrow[r] * corr + sum;
            crow[r] = corr;
        }
        __syncthreads();

        // Rescale accumulators, then O += P @ V
#pragma unroll
        for (int i = 0; i < 4; ++i) {
            float cr = crow[r0 + i];
#pragma unroll
            for (int j = 0; j < 8; ++j) acc[i][j] *= cr;
        }
#pragma unroll 4
        for (int k = 0; k < 64; ++k) {
            float4 v0 = *(const float4*)(Vs + k * 128 + co);
            float4 v1 = *(const float4*)(Vs + k * 128 + co + 4);
#pragma unroll
            for (int i = 0; i < 4; ++i) {
                float p = Ss[(r0 + i) * 65 + k];
                acc[i][0] = fmaf(p, v0.x, acc[i][0]);
                acc[i][1] = fmaf(p, v0.y, acc[i][1]);
                acc[i][2] = fmaf(p, v0.z, acc[i][2]);
                acc[i][3] = fmaf(p, v0.w, acc[i][3]);
                acc[i][4] = fmaf(p, v1.x, acc[i][4]);
                acc[i][5] = fmaf(p, v1.y, acc[i][5]);
                acc[i][6] = fmaf(p, v1.z, acc[i][6]);
                acc[i][7] = fmaf(p, v1.w, acc[i][7]);
            }
        }
    }

    // Epilogue: O /= l, write to attn [8192, 2048]
#pragma unroll
    for (int i = 0; i < 4; ++i) {
        int r = r0 + i;
        float inv = 1.f / lrow[r];
        size_t orow = (size_t)(b * SEQ + q0 + r) * HID + h * HD + co;
        float4 o0 = make_float4(acc[i][0] * inv, acc[i][1] * inv,
                                acc[i][2] * inv, acc[i][3] * inv);
        float4 o1 = make_float4(acc[i][4] * inv, acc[i][5] * inv,
                                acc[i][6] * inv, acc[i][7] * inv);
        *(float4*)(attn + orow)     = o0;
        *(float4*)(attn + orow + 4) = o1;
    }
}

// ---------------------------------------------------------------------------
extern "C" void kernel_launch(void* const* d_in, const int* in_sizes, int n_in,
                              void* d_out, int out_size)
{
    (void)in_sizes; (void)n_in; (void)out_size;
    const float* hs      = (const float*)d_in[0];
    const float* w_qkv   = (const float*)d_in[1];
    const float* b_qkv   = (const float*)d_in[2];
    const float* w_dense = (const float*)d_in[3];
    const float* b_dense = (const float*)d_in[4];
    float* out = (float*)d_out;

    float *qkv = nullptr, *attn = nullptr;
    cudaGetSymbolAddress((void**)&qkv, g_qkv);
    cudaGetSymbolAddress((void**)&attn, g_attn);

    dim3 blk(256);

    // 1) QKV projection: [8192,6144] = hs @ w_qkv^T + b_qkv
    dim3 g1(QKVN / 128, MROWS / 128);
    sgemm_bias_kernel<<<g1, blk>>>(hs, w_qkv, b_qkv, qkv, QKVN, HID);

    // 2) Causal flash attention
    int smem = (3 * 64 * 128 + 64 * 65 + 3 * 64) * (int)sizeof(float);
    cudaFuncSetAttribute(flash_attn_kernel,
                         cudaFuncAttributeMaxDynamicSharedMemorySize, smem);
    dim3 g2(SEQ / 64, NH, BATCH);
    flash_attn_kernel<<<g2, blk, smem>>>(qkv, attn);

    // 3) Dense projection: [8192,2048] = attn @ w_dense^T + b_dense
    dim3 g3(HID / 128, MROWS / 128);
    sgemm_bias_kernel<<<g3, blk>>>(attn, w_dense, b_dense, out, HID, HID);
}

// round 3
// speedup vs baseline: 1.3438x; 1.3438x over previous
#include <cuda_runtime.h>
#include <cuda_bf16.h>
#include <math.h>
#include <stdint.h>

#define HID   2048
#define NH    16
#define HD    128
#define BATCH 4
#define SEQ   2048
#define MROWS (BATCH*SEQ)     // 8192
#define QKVN  (3*HID)         // 6144
#define KSPLIT (3*HID)        // 6144 = K' for split GEMM

// ---------------------------------------------------------------------------
// Scratch (__device__ globals; allocation-guard-safe)
// ---------------------------------------------------------------------------
__device__ __align__(1024) __nv_bfloat16 g_ab[(size_t)MROWS * KSPLIT];     // A' (hi|lo|hi)
__device__ __align__(1024) __nv_bfloat16 g_bqkv[(size_t)QKVN * KSPLIT];    // B' qkv (hi|hi|lo)
__device__ __align__(1024) __nv_bfloat16 g_bdense[(size_t)HID * KSPLIT];   // B' dense
__device__ __align__(1024) float g_qkv[(size_t)MROWS * QKVN];              // fp32 qkv
__device__ __align__(1024) float g_attn[(size_t)MROWS * HID];              // fp32 attn out

// ---------------------------------------------------------------------------
// PTX helpers (all portable: sm_80+/sm_75+)
// ---------------------------------------------------------------------------
__device__ __forceinline__ uint32_t smem_u32(const void* p) {
    uint32_t a;
    asm("{ .reg .u64 t; cvta.to.shared.u64 t, %1; cvt.u32.u64 %0, t; }"
        : "=r"(a) : "l"(p));
    return a;
}
__device__ __forceinline__ void cp16(uint32_t s, const void* g) {
    asm volatile("cp.async.cg.shared.global [%0], [%1], 16;" :: "r"(s), "l"(g));
}
__device__ __forceinline__ void cp_commit() {
    asm volatile("cp.async.commit_group;" ::: "memory");
}
template<int N> __device__ __forceinline__ void cp_wait() {
    asm volatile("cp.async.wait_group %0;" :: "n"(N) : "memory");
}
__device__ __forceinline__ void ldsm_x4(uint32_t& r0, uint32_t& r1,
                                        uint32_t& r2, uint32_t& r3, uint32_t addr) {
    asm volatile("ldmatrix.sync.aligned.m8n8.x4.shared.b16 {%0,%1,%2,%3}, [%4];"
                 : "=r"(r0), "=r"(r1), "=r"(r2), "=r"(r3) : "r"(addr));
}
__device__ __forceinline__ void mma_bf16(float& d0, float& d1, float& d2, float& d3,
                                         uint32_t a0, uint32_t a1, uint32_t a2, uint32_t a3,
                                         uint32_t b0, uint32_t b1) {
    asm volatile(
        "mma.sync.aligned.m16n8k16.row.col.f32.bf16.bf16.f32 "
        "{%0,%1,%2,%3}, {%4,%5,%6,%7}, {%8,%9}, {%0,%1,%2,%3};"
        : "+f"(d0), "+f"(d1), "+f"(d2), "+f"(d3)
        : "r"(a0), "r"(a1), "r"(a2), "r"(a3), "r"(b0), "r"(b1));
}

// ---------------------------------------------------------------------------
// Split kernel: fp32 [R, 2048] -> bf16 [R, 6144]:
//   mode 0 (A side): [hi | lo | hi],  mode 1 (B side): [hi | hi | lo]
// ---------------------------------------------------------------------------
__global__ __launch_bounds__(256)
void split_kernel(const float4* __restrict__ in, __nv_bfloat162* __restrict__ out,
                  int nvec, int mode)
{
    int i = blockIdx.x * blockDim.x + threadIdx.x;
    if (i >= nvec) return;
    float4 v = in[i];
    int r = i >> 9;
    int c = (i & 511) << 2;

    __nv_bfloat16 h0 = __float2bfloat16(v.x);
    __nv_bfloat16 h1 = __float2bfloat16(v.y);
    __nv_bfloat16 h2 = __float2bfloat16(v.z);
    __nv_bfloat16 h3 = __float2bfloat16(v.w);
    __nv_bfloat16 l0 = __float2bfloat16(v.x - __bfloat162float(h0));
    __nv_bfloat16 l1 = __float2bfloat16(v.y - __bfloat162float(h1));
    __nv_bfloat16 l2 = __float2bfloat16(v.z - __bfloat162float(h2));
    __nv_bfloat16 l3 = __float2bfloat16(v.w - __bfloat162float(h3));

    __nv_bfloat162 hA = __halves2bfloat162(h0, h1);
    __nv_bfloat162 hB = __halves2bfloat162(h2, h3);
    __nv_bfloat162 lA = __halves2bfloat162(l0, l1);
    __nv_bfloat162 lB = __halves2bfloat162(l2, l3);

    size_t base = (size_t)r * 3072 + (c >> 1);
    if (mode == 0) {
        out[base]        = hA; out[base + 1]    = hB;
        out[base + 1024] = lA; out[base + 1025] = lB;
        out[base + 2048] = hA; out[base + 2049] = hB;
    } else {
        out[base]        = hA; out[base + 1]    = hB;
        out[base + 1024] = hA; out[base + 1025] = hB;
        out[base + 2048] = lA; out[base + 2049] = lB;
    }
}

// ---------------------------------------------------------------------------
// bf16 HMMA GEMM: C[M,N] = A'[M,6144] @ B'[N,6144]^T + bias (fp32 out)
// CTA 128x256, 8 warps (wm 0..1, wn 0..3), warp tile 64x64.
// K-chunk 32, 4-stage cp.async pipeline.
// Smem rows padded to 40 bf16 (80B) -> conflict-free ldmatrix.
// Grid: (N/256, M/128), 256 threads.
// ---------------------------------------------------------------------------
#define CHUNKS  (KSPLIT / 32)     // 192
#define STAGES  4
#define ROWB    80                // padded row bytes (32 data + 8 pad bf16)
#define A_BYTES (128 * ROWB)      // 10240
#define B_BYTES (256 * ROWB)      // 20480
#define STAGE_B (A_BYTES + B_BYTES)
#define GEMM_SMEM (STAGES * STAGE_B)  // 122880

__global__ __launch_bounds__(256, 1)
void gemm_mma_kernel(const __nv_bfloat16* __restrict__ A,
                     const __nv_bfloat16* __restrict__ B,
                     const float* __restrict__ bias,
                     float* __restrict__ C, int N)
{
    extern __shared__ __align__(128) char smem[];
    const uint32_t sb = smem_u32(smem);

    const int tid  = threadIdx.x;
    const int wid  = tid >> 5;
    const int lane = tid & 31;
    const int wm   = wid & 1;        // 0..1  (m block of 64)
    const int wn   = wid >> 1;       // 0..3  (n block of 64)
    const int m0   = blockIdx.y * 128;
    const int n0   = blockIdx.x * 256;

    // ldmatrix lane address components
    const int a_row = (lane & 7) + ((lane >> 3) & 1) * 8;  // 0..15
    const int a_k8  = (lane >> 4) & 1;                      // 0..1
    const int b_nrw = (lane & 7) + ((lane >> 4) & 1) * 8;   // matrix pair: n row
    const int b_k8  = (lane >> 3) & 1;                      // k8 within pair

    // gmem load assignments (per stage): A 2 ops, B 4 ops per thread
    const int ar[2] = { (tid + 0) >> 2, (tid + 256) >> 2 };
    const int ac    = tid & 3;

    float acc[4][8][4];
#pragma unroll
    for (int i = 0; i < 4; ++i)
#pragma unroll
        for (int j = 0; j < 8; ++j)
#pragma unroll
            for (int q = 0; q < 4; ++q) acc[i][j][q] = 0.f;

    // ---- stage loader ----
    auto load_stage = [&](int slot, int kk) {
        const uint32_t sa  = sb + slot * STAGE_B;
        const uint32_t sbb = sa + A_BYTES;
        const __nv_bfloat16* Ak = A + (size_t)m0 * KSPLIT + kk * 32;
        const __nv_bfloat16* Bk = B + (size_t)n0 * KSPLIT + kk * 32;
#pragma unroll
        for (int i = 0; i < 2; ++i) {
            int r = ar[i];
            cp16(sa + r * ROWB + ac * 16, Ak + (size_t)r * KSPLIT + ac * 8);
        }
#pragma unroll
        for (int i = 0; i < 4; ++i) {
            int idx = tid + i * 256;
            int r = idx >> 2, c = idx & 3;
            cp16(sbb + r * ROWB + c * 16, Bk + (size_t)r * KSPLIT + c * 8);
        }
    };

    // prologue: fill 3 stages
#pragma unroll
    for (int s = 0; s < STAGES - 1; ++s) { load_stage(s, s); cp_commit(); }

    for (int k = 0; k < CHUNKS; ++k) {
        const int s = k & (STAGES - 1);
        cp_wait<STAGES - 2>();
        __syncthreads();

        if (k + STAGES - 1 < CHUNKS) load_stage((k + STAGES - 1) & (STAGES - 1),
                                                 k + STAGES - 1);
        cp_commit();

        const uint32_t sa  = sb + s * STAGE_B + (wm * 64) * ROWB;
        const uint32_t sbb = sb + s * STAGE_B + A_BYTES + (wn * 64) * ROWB;

#pragma unroll
        for (int kk = 0; kk < 2; ++kk) {           // two k16 per chunk
            uint32_t a[4][4];
            uint32_t bfr[8][2];
#pragma unroll
            for (int mt = 0; mt < 4; ++mt) {
                uint32_t addr = sa + (mt * 16 + a_row) * ROWB + (kk * 2 + a_k8) * 16;
                ldsm_x4(a[mt][0], a[mt][1], a[mt][2], a[mt][3], addr);
            }
#pragma unroll
            for (int np = 0; np < 4; ++np) {       // n-tile pairs
                uint32_t addr = sbb + (np * 16 + b_nrw) * ROWB + (kk * 2 + b_k8) * 16;
                uint32_t r0, r1, r2, r3;
                ldsm_x4(r0, r1, r2, r3, addr);
                bfr[np * 2 + 0][0] = r0; bfr[np * 2 + 0][1] = r1;
                bfr[np * 2 + 1][0] = r2; bfr[np * 2 + 1][1] = r3;
            }
#pragma unroll
            for (int mt = 0; mt < 4; ++mt)
#pragma unroll
                for (int nt = 0; nt < 8; ++nt)
                    mma_bf16(acc[mt][nt][0], acc[mt][nt][1],
                             acc[mt][nt][2], acc[mt][nt][3],
                             a[mt][0], a[mt][1], a[mt][2], a[mt][3],
                             bfr[nt][0], bfr[nt][1]);
        }
    }

    // ---- epilogue ----
    const int g  = lane >> 2;
    const int ti = lane & 3;
#pragma unroll
    for (int mt = 0; mt < 4; ++mt) {
        const int row = m0 + wm * 64 + mt * 16 + g;
#pragma unroll
        for (int nt = 0; nt < 8; ++nt) {
            const int col = n0 + wn * 64 + nt * 8 + ti * 2;
            float2 bv = *(const float2*)(bias + col);
            float2 o0 = make_float2(acc[mt][nt][0] + bv.x, acc[mt][nt][1] + bv.y);
            float2 o1 = make_float2(acc[mt][nt][2] + bv.x, acc[mt][nt][3] + bv.y);
            *(float2*)(C + (size_t)row * N + col)       = o0;
            *(float2*)(C + (size_t)(row + 8) * N + col) = o1;
        }
    }
}

// ---------------------------------------------------------------------------
// Flash attention (fp32, online softmax, causal), Bq=Bk=64, D=128.
// ---------------------------------------------------------------------------
__global__ __launch_bounds__(256)
void flash_attn_kernel(const float* __restrict__ qkv,
                       float* __restrict__ attn)
{
    extern __shared__ float sm[];
    float* Qs   = sm;
    float* Ks   = Qs + 64 * 128;
    float* Vs   = Ks + 64 * 128;
    float* Ss   = Vs + 64 * 128;
    float* mrow = Ss + 64 * 65;
    float* lrow = mrow + 64;
    float* crow = lrow + 64;

    const int qt  = blockIdx.x;
    const int h   = blockIdx.y;
    const int b   = blockIdx.z;
    const int tid = threadIdx.x;
    const int ty  = tid >> 4, tx = tid & 15;
    const int r0  = ty << 2;
    const int cs  = tx << 2;
    const int co  = tx << 3;
    const int q0  = qt * 64;
    const float scale = 0.08838834764831845f;

    const float* base = qkv + (size_t)b * SEQ * QKVN;

    for (int i = tid; i < 64 * 32; i += 256) {
        int r = i >> 5, c4 = (i & 31) << 2;
        *(float4*)(Qs + r * 128 + c4) =
            *(const float4*)(base + (size_t)(q0 + r) * QKVN + h * HD + c4);
    }
    if (tid < 64) { mrow[tid] = -INFINITY; lrow[tid] = 0.f; }

    float acc[4][8];
#pragma unroll
    for (int i = 0; i < 4; ++i)
#pragma unroll
        for (int j = 0; j < 8; ++j) acc[i][j] = 0.f;

    for (int kt = 0; kt <= qt; ++kt) {
        const int k0 = kt * 64;
        __syncthreads();
        for (int i = tid; i < 64 * 32; i += 256) {
            int r = i >> 5, c4 = (i & 31) << 2;
            const float* p = base + (size_t)(k0 + r) * QKVN + HID + h * HD + c4;
            *(float4*)(Ks + r * 128 + c4) = *(const float4*)(p);
            *(float4*)(Vs + r * 128 + c4) = *(const float4*)(p + HID);
        }
        __syncthreads();

        float s[4][4];
#pragma unroll
        for (int i = 0; i < 4; ++i)
#pragma unroll
            for (int j = 0; j < 4; ++j) s[i][j] = 0.f;

        for (int d = 0; d < 128; d += 4) {
            float4 qv[4], kv[4];
#pragma unroll
            for (int i = 0; i < 4; ++i)
                qv[i] = *(const float4*)(Qs + (r0 + i) * 128 + d);
#pragma unroll
            for (int j = 0; j < 4; ++j)
                kv[j] = *(const float4*)(Ks + (cs + j) * 128 + d);
#pragma unroll
            for (int i = 0; i < 4; ++i)
#pragma unroll
                for (int j = 0; j < 4; ++j)
                    s[i][j] += qv[i].x * kv[j].x + qv[i].y * kv[j].y
                             + qv[i].z * kv[j].z + qv[i].w * kv[j].w;
        }
#pragma unroll
        for (int i = 0; i < 4; ++i)
#pragma unroll
            for (int j = 0; j < 4; ++j) {
                int qg = q0 + r0 + i, kg = k0 + cs + j;
                Ss[(r0 + i) * 65 + cs + j] =
                    (kg <= qg) ? s[i][j] * scale : -INFINITY;
            }
        __syncthreads();

        if (tid < 64) {
            const int r = tid;
            float mold = mrow[r];
            float mx = mold;
            for (int c = 0; c < 64; ++c) mx = fmaxf(mx, Ss[r * 65 + c]);
            float corr = __expf(mold - mx);
            float sum = 0.f;
            for (int c = 0; c < 64; ++c) {
                float p = __expf(Ss[r * 65 + c] - mx);
                Ss[r * 65 + c] = p;
                sum += p;
            }
            mrow[r] = mx;
            lrow[r] = lrow[r] * corr + sum;
            crow[r] = corr;
        }
        __syncthreads();

#pragma unroll
        for (int i = 0; i < 4; ++i) {
            float cr = crow[r0 + i];
#pragma unroll
            for (int j = 0; j < 8; ++j) acc[i][j] *= cr;
        }
#pragma unroll 4
        for (int k = 0; k < 64; ++k) {
            float4 v0 = *(const float4*)(Vs + k * 128 + co);
            float4 v1 = *(const float4*)(Vs + k * 128 + co + 4);
#pragma unroll
            for (int i = 0; i < 4; ++i) {
                float p = Ss[(r0 + i) * 65 + k];
                acc[i][0] = fmaf(p, v0.x, acc[i][0]);
                acc[i][1] = fmaf(p, v0.y, acc[i][1]);
                acc[i][2] = fmaf(p, v0.z, acc[i][2]);
                acc[i][3] = fmaf(p, v0.w, acc[i][3]);
                acc[i][4] = fmaf(p, v1.x, acc[i][4]);
                acc[i][5] = fmaf(p, v1.y, acc[i][5]);
                acc[i][6] = fmaf(p, v1.z, acc[i][6]);
                acc[i][7] = fmaf(p, v1.w, acc[i][7]);
            }
        }
    }

#pragma unroll
    for (int i = 0; i < 4; ++i) {
        int r = r0 + i;
        float inv = 1.f / lrow[r];
        size_t orow = (size_t)(b * SEQ + q0 + r) * HID + h * HD + co;
        float4 o0 = make_float4(acc[i][0] * inv, acc[i][1] * inv,
                                acc[i][2] * inv, acc[i][3] * inv);
        float4 o1 = make_float4(acc[i][4] * inv, acc[i][5] * inv,
                                acc[i][6] * inv, acc[i][7] * inv);
        *(float4*)(attn + orow)     = o0;
        *(float4*)(attn + orow + 4) = o1;
    }
}

// ---------------------------------------------------------------------------
// Host side
// ---------------------------------------------------------------------------
extern "C" void kernel_launch(void* const* d_in, const int* in_sizes, int n_in,
                              void* d_out, int out_size)
{
    (void)in_sizes; (void)n_in; (void)out_size;
    const float* hs      = (const float*)d_in[0];
    const float* w_qkv   = (const float*)d_in[1];
    const float* b_qkv   = (const float*)d_in[2];
    const float* w_dense = (const float*)d_in[3];
    const float* b_dense = (const float*)d_in[4];
    float* out = (float*)d_out;

    void *p_ab, *p_bqkv, *p_bdense, *p_qkv, *p_attn;
    cudaGetSymbolAddress(&p_ab, g_ab);
    cudaGetSymbolAddress(&p_bqkv, g_bqkv);
    cudaGetSymbolAddress(&p_bdense, g_bdense);
    cudaGetSymbolAddress(&p_qkv, g_qkv);
    cudaGetSymbolAddress(&p_attn, g_attn);

    static bool attr_done = false;
    if (!attr_done) {
        cudaFuncSetAttribute(gemm_mma_kernel,
                             cudaFuncAttributeMaxDynamicSharedMemorySize, GEMM_SMEM);
        cudaFuncSetAttribute(flash_attn_kernel,
                             cudaFuncAttributeMaxDynamicSharedMemorySize,
                             (3 * 64 * 128 + 64 * 65 + 3 * 64) * (int)sizeof(float));
        attr_done = true;
    }

    // 1) split inputs to bf16 hi/lo
    {
        int nv = MROWS * HID / 4;
        split_kernel<<<(nv + 255) / 256, 256>>>((const float4*)hs,
                                                (__nv_bfloat162*)p_ab, nv, 0);
        nv = QKVN * HID / 4;
        split_kernel<<<(nv + 255) / 256, 256>>>((const float4*)w_qkv,
                                                (__nv_bfloat162*)p_bqkv, nv, 1);
        nv = HID * HID / 4;
        split_kernel<<<(nv + 255) / 256, 256>>>((const float4*)w_dense,
                                                (__nv_bfloat162*)p_bdense, nv, 1);
    }

    // 2) QKV projection (tensor cores)
    {
        dim3 g(QKVN / 256, MROWS / 128);
        gemm_mma_kernel<<<g, 256, GEMM_SMEM>>>(
            (const __nv_bfloat16*)p_ab, (const __nv_bfloat16*)p_bqkv,
            b_qkv, (float*)p_qkv, QKVN);
    }

    // 3) Causal flash attention
    {
        int smem = (3 * 64 * 128 + 64 * 65 + 3 * 64) * (int)sizeof(float);
        dim3 g(SEQ / 64, NH, BATCH);
        flash_attn_kernel<<<g, 256, smem>>>((const float*)p_qkv, (float*)p_attn);
    }

    // 4) split attention output, dense projection
    {
        int nv = MROWS * HID / 4;
        split_kernel<<<(nv + 255) / 256, 256>>>((const float4*)p_attn,
                                                (__nv_bfloat162*)p_ab, nv, 0);
        dim3 g(HID / 256, MROWS / 128);
        gemm_mma_kernel<<<g, 256, GEMM_SMEM>>>(
            (const __nv_bfloat16*)p_ab, (const __nv_bfloat16*)p_bdense,
            b_dense, out, HID);
    }
}

// round 4
// speedup vs baseline: 3.4243x; 2.5481x over previous
#include <cuda_runtime.h>
#include <cuda_bf16.h>
#include <math.h>
#include <stdint.h>

#define HID   2048
#define NH    16
#define HD    128
#define BATCH 4
#define SEQ   2048
#define MROWS (BATCH*SEQ)     // 8192
#define QKVN  (3*HID)         // 6144
#define KSPLIT (3*HID)        // 6144

// ---------------------------------------------------------------------------
// Scratch
// ---------------------------------------------------------------------------
__device__ __align__(1024) __nv_bfloat16 g_ab[(size_t)MROWS * KSPLIT];
__device__ __align__(1024) __nv_bfloat16 g_bqkv[(size_t)QKVN * KSPLIT];
__device__ __align__(1024) __nv_bfloat16 g_bdense[(size_t)HID * KSPLIT];
__device__ __align__(1024) float g_qkv[(size_t)MROWS * QKVN];
__device__ __align__(1024) float g_attn[(size_t)MROWS * HID];
// per-head split layout: [sel(q,k,v)][b][h][s][hi128|lo128]
__device__ __align__(1024) __nv_bfloat16 g_hsplit[(size_t)3 * BATCH * NH * SEQ * 256];

// ---------------------------------------------------------------------------
// PTX helpers (portable sm_80+)
// ---------------------------------------------------------------------------
__device__ __forceinline__ uint32_t smem_u32(const void* p) {
    uint32_t a;
    asm("{ .reg .u64 t; cvta.to.shared.u64 t, %1; cvt.u32.u64 %0, t; }"
        : "=r"(a) : "l"(p));
    return a;
}
__device__ __forceinline__ void cp16(uint32_t s, const void* g) {
    asm volatile("cp.async.cg.shared.global [%0], [%1], 16;" :: "r"(s), "l"(g));
}
__device__ __forceinline__ void cp_commit() {
    asm volatile("cp.async.commit_group;" ::: "memory");
}
template<int N> __device__ __forceinline__ void cp_wait() {
    asm volatile("cp.async.wait_group %0;" :: "n"(N) : "memory");
}
__device__ __forceinline__ void ldsm_x4(uint32_t& r0, uint32_t& r1,
                                        uint32_t& r2, uint32_t& r3, uint32_t addr) {
    asm volatile("ldmatrix.sync.aligned.m8n8.x4.shared.b16 {%0,%1,%2,%3}, [%4];"
                 : "=r"(r0), "=r"(r1), "=r"(r2), "=r"(r3) : "r"(addr));
}
__device__ __forceinline__ void ldsm_x4_t(uint32_t& r0, uint32_t& r1,
                                          uint32_t& r2, uint32_t& r3, uint32_t addr) {
    asm volatile("ldmatrix.sync.aligned.m8n8.x4.trans.shared.b16 {%0,%1,%2,%3}, [%4];"
                 : "=r"(r0), "=r"(r1), "=r"(r2), "=r"(r3) : "r"(addr));
}
__device__ __forceinline__ void mma_bf16(float& d0, float& d1, float& d2, float& d3,
                                         uint32_t a0, uint32_t a1, uint32_t a2, uint32_t a3,
                                         uint32_t b0, uint32_t b1) {
    asm volatile(
        "mma.sync.aligned.m16n8k16.row.col.f32.bf16.bf16.f32 "
        "{%0,%1,%2,%3}, {%4,%5,%6,%7}, {%8,%9}, {%0,%1,%2,%3};"
        : "+f"(d0), "+f"(d1), "+f"(d2), "+f"(d3)
        : "r"(a0), "r"(a1), "r"(a2), "r"(a3), "r"(b0), "r"(b1));
}
__device__ __forceinline__ uint32_t pack_bf16(float a, float b) {
    __nv_bfloat162 t = __float22bfloat162_rn(make_float2(a, b));
    return *(uint32_t*)&t;
}
__device__ __forceinline__ float2 unpack_bf16(uint32_t u) {
    __nv_bfloat162 t = *(__nv_bfloat162*)&u;
    return __bfloat1622float2(t);
}

// ---------------------------------------------------------------------------
// Split kernel (unchanged)
// ---------------------------------------------------------------------------
__global__ __launch_bounds__(256)
void split_kernel(const float4* __restrict__ in, __nv_bfloat162* __restrict__ out,
                  int nvec, int mode)
{
    int i = blockIdx.x * blockDim.x + threadIdx.x;
    if (i >= nvec) return;
    float4 v = in[i];
    int r = i >> 9;
    int c = (i & 511) << 2;

    __nv_bfloat16 h0 = __float2bfloat16(v.x);
    __nv_bfloat16 h1 = __float2bfloat16(v.y);
    __nv_bfloat16 h2 = __float2bfloat16(v.z);
    __nv_bfloat16 h3 = __float2bfloat16(v.w);
    __nv_bfloat16 l0 = __float2bfloat16(v.x - __bfloat162float(h0));
    __nv_bfloat16 l1 = __float2bfloat16(v.y - __bfloat162float(h1));
    __nv_bfloat16 l2 = __float2bfloat16(v.z - __bfloat162float(h2));
    __nv_bfloat16 l3 = __float2bfloat16(v.w - __bfloat162float(h3));

    __nv_bfloat162 hA = __halves2bfloat162(h0, h1);
    __nv_bfloat162 hB = __halves2bfloat162(h2, h3);
    __nv_bfloat162 lA = __halves2bfloat162(l0, l1);
    __nv_bfloat162 lB = __halves2bfloat162(l2, l3);

    size_t base = (size_t)r * 3072 + (c >> 1);
    if (mode == 0) {
        out[base]        = hA; out[base + 1]    = hB;
        out[base + 1024] = lA; out[base + 1025] = lB;
        out[base + 2048] = hA; out[base + 2049] = hB;
    } else {
        out[base]        = hA; out[base + 1]    = hB;
        out[base + 1024] = hA; out[base + 1025] = hB;
        out[base + 2048] = lA; out[base + 2049] = lB;
    }
}

// ---------------------------------------------------------------------------
// Prep: fp32 qkv [8192,6144] -> per-head bf16 split g_hsplit
// ---------------------------------------------------------------------------
__global__ __launch_bounds__(256)
void prep_split_kernel(const float4* __restrict__ qkv, __nv_bfloat162* __restrict__ out)
{
    int i = blockIdx.x * blockDim.x + threadIdx.x;
    if (i >= MROWS * 1536) return;
    int rr  = i / 1536;
    int col = (i - rr * 1536) * 4;
    int sel = col >> 11;
    int wcol = col & 2047;
    int h = wcol >> 7, d = wcol & 127;
    int b = rr >> 11, s = rr & 2047;

    float4 v = qkv[i];
    __nv_bfloat16 h0 = __float2bfloat16(v.x);
    __nv_bfloat16 h1 = __float2bfloat16(v.y);
    __nv_bfloat16 h2 = __float2bfloat16(v.z);
    __nv_bfloat16 h3 = __float2bfloat16(v.w);
    __nv_bfloat16 l0 = __float2bfloat16(v.x - __bfloat162float(h0));
    __nv_bfloat16 l1 = __float2bfloat16(v.y - __bfloat162float(h1));
    __nv_bfloat16 l2 = __float2bfloat16(v.z - __bfloat162float(h2));
    __nv_bfloat16 l3 = __float2bfloat16(v.w - __bfloat162float(h3));

    size_t base = ((((size_t)sel * BATCH + b) * NH + h) * SEQ + s) * 256 + d;
    out[(base) >> 1]       = __halves2bfloat162(h0, h1);
    out[(base + 2) >> 1]   = __halves2bfloat162(h2, h3);
    out[(base + 128) >> 1] = __halves2bfloat162(l0, l1);
    out[(base + 130) >> 1] = __halves2bfloat162(l2, l3);
}

// ---------------------------------------------------------------------------
// bf16 HMMA GEMM (unchanged from R3)
// ---------------------------------------------------------------------------
#define CHUNKS  (KSPLIT / 32)
#define STAGES  4
#define ROWB    80
#define A_BYTES (128 * ROWB)
#define B_BYTES (256 * ROWB)
#define STAGE_B (A_BYTES + B_BYTES)
#define GEMM_SMEM (STAGES * STAGE_B)

__global__ __launch_bounds__(256, 1)
void gemm_mma_kernel(const __nv_bfloat16* __restrict__ A,
                     const __nv_bfloat16* __restrict__ B,
                     const float* __restrict__ bias,
                     float* __restrict__ C, int N)
{
    extern __shared__ __align__(128) char smem[];
    const uint32_t sb = smem_u32(smem);

    const int tid  = threadIdx.x;
    const int wid  = tid >> 5;
    const int lane = tid & 31;
    const int wm   = wid & 1;
    const int wn   = wid >> 1;
    const int m0   = blockIdx.y * 128;
    const int n0   = blockIdx.x * 256;

    const int a_row = (lane & 7) + ((lane >> 3) & 1) * 8;
    const int a_k8  = (lane >> 4) & 1;
    const int b_nrw = (lane & 7) + ((lane >> 4) & 1) * 8;
    const int b_k8  = (lane >> 3) & 1;

    const int ar[2] = { (tid + 0) >> 2, (tid + 256) >> 2 };
    const int ac    = tid & 3;

    float acc[4][8][4];
#pragma unroll
    for (int i = 0; i < 4; ++i)
#pragma unroll
        for (int j = 0; j < 8; ++j)
#pragma unroll
            for (int q = 0; q < 4; ++q) acc[i][j][q] = 0.f;

    auto load_stage = [&](int slot, int kk) {
        const uint32_t sa  = sb + slot * STAGE_B;
        const uint32_t sbb = sa + A_BYTES;
        const __nv_bfloat16* Ak = A + (size_t)m0 * KSPLIT + kk * 32;
        const __nv_bfloat16* Bk = B + (size_t)n0 * KSPLIT + kk * 32;
#pragma unroll
        for (int i = 0; i < 2; ++i) {
            int r = ar[i];
            cp16(sa + r * ROWB + ac * 16, Ak + (size_t)r * KSPLIT + ac * 8);
        }
#pragma unroll
        for (int i = 0; i < 4; ++i) {
            int idx = tid + i * 256;
            int r = idx >> 2, c = idx & 3;
            cp16(sbb + r * ROWB + c * 16, Bk + (size_t)r * KSPLIT + c * 8);
        }
    };

#pragma unroll
    for (int s = 0; s < STAGES - 1; ++s) { load_stage(s, s); cp_commit(); }

    for (int k = 0; k < CHUNKS; ++k) {
        const int s = k & (STAGES - 1);
        cp_wait<STAGES - 2>();
        __syncthreads();

        if (k + STAGES - 1 < CHUNKS) load_stage((k + STAGES - 1) & (STAGES - 1),
                                                 k + STAGES - 1);
        cp_commit();

        const uint32_t sa  = sb + s * STAGE_B + (wm * 64) * ROWB;
        const uint32_t sbb = sb + s * STAGE_B + A_BYTES + (wn * 64) * ROWB;

#pragma unroll
        for (int kk = 0; kk < 2; ++kk) {
            uint32_t a[4][4];
            uint32_t bfr[8][2];
#pragma unroll
            for (int mt = 0; mt < 4; ++mt) {
                uint32_t addr = sa + (mt * 16 + a_row) * ROWB + (kk * 2 + a_k8) * 16;
                ldsm_x4(a[mt][0], a[mt][1], a[mt][2], a[mt][3], addr);
            }
#pragma unroll
            for (int np = 0; np < 4; ++np) {
                uint32_t addr = sbb + (np * 16 + b_nrw) * ROWB + (kk * 2 + b_k8) * 16;
                uint32_t r0, r1, r2, r3;
                ldsm_x4(r0, r1, r2, r3, addr);
                bfr[np * 2 + 0][0] = r0; bfr[np * 2 + 0][1] = r1;
                bfr[np * 2 + 1][0] = r2; bfr[np * 2 + 1][1] = r3;
            }
#pragma unroll
            for (int mt = 0; mt < 4; ++mt)
#pragma unroll
                for (int nt = 0; nt < 8; ++nt)
                    mma_bf16(acc[mt][nt][0], acc[mt][nt][1],
                             acc[mt][nt][2], acc[mt][nt][3],
                             a[mt][0], a[mt][1], a[mt][2], a[mt][3],
                             bfr[nt][0], bfr[nt][1]);
        }
    }

    const int g  = lane >> 2;
    const int ti = lane & 3;
#pragma unroll
    for (int mt = 0; mt < 4; ++mt) {
        const int row = m0 + wm * 64 + mt * 16 + g;
#pragma unroll
        for (int nt = 0; nt < 8; ++nt) {
            const int col = n0 + wn * 64 + nt * 8 + ti * 2;
            float2 bv = *(const float2*)(bias + col);
            float2 o0 = make_float2(acc[mt][nt][0] + bv.x, acc[mt][nt][1] + bv.y);
            float2 o1 = make_float2(acc[mt][nt][2] + bv.x, acc[mt][nt][3] + bv.y);
            *(float2*)(C + (size_t)row * N + col)       = o0;
            *(float2*)(C + (size_t)(row + 8) * N + col) = o1;
        }
    }
}

// ---------------------------------------------------------------------------
// Flash attention, bf16 HMMA, split precision, causal.
// Bq=128 (8 warps x 16 rows), Bk=64, D=128.
// smem: 2 stages x (Kh,Kl,Vh,Vl) tiles 64x(128+8)bf16 rows (272B).
// ---------------------------------------------------------------------------
#define FROWB 272                       // 136 bf16 per row
#define FTILE (64 * FROWB)              // 17408
#define FSTAGE (4 * FTILE)              // 69632
#define FLASH_SMEM (2 * FSTAGE)         // 139264

__global__ __launch_bounds__(256, 1)
void flash_mma_kernel(const __nv_bfloat16* __restrict__ gs,
                      float* __restrict__ attn)
{
    extern __shared__ __align__(128) char smem[];
    const uint32_t sb = smem_u32(smem);

    const int bid = blockIdx.x;
    const int qt  = 15 - (bid >> 6);       // descending qt (longest first)
    const int sub = bid & 63;
    const int h   = sub & 15;
    const int b   = sub >> 4;
    const int q0  = qt * 128;
    const int nkt = 2 * qt + 2;

    const int tid  = threadIdx.x;
    const int w    = tid >> 5;
    const int lane = tid & 31;
    const int g    = lane >> 2;
    const int ti   = lane & 3;
    const float scale = 0.08838834764831845f;

    const __nv_bfloat16* gq = gs + (((size_t)0 * BATCH + b) * NH + h) * SEQ * 256;
    const __nv_bfloat16* gk = gs + (((size_t)1 * BATCH + b) * NH + h) * SEQ * 256;
    const __nv_bfloat16* gv = gs + (((size_t)2 * BATCH + b) * NH + h) * SEQ * 256;

    // ---- load Q (hi+lo) into stage0 smem ----
    {
#pragma unroll
        for (int i = 0; i < 16; ++i) {
            int idx = tid + i * 256;          // < 4096
            int r = idx >> 5;
            int rem = idx & 31;
            int part = rem >> 4;
            int c = rem & 15;
            cp16(sb + part * (128 * FROWB) + r * FROWB + c * 16,
                 gq + ((size_t)(q0 + r)) * 256 + part * 128 + c * 8);
        }
        cp_commit();
        cp_wait<0>();
        __syncthreads();
    }

    // ---- Q fragments to registers ----
    uint32_t qh[8][4], qlr[8][4];
    {
        int r  = w * 16 + (lane & 15);
        int cb = ((lane >> 4) & 1) * 16;
#pragma unroll
        for (int c = 0; c < 8; ++c) {
            ldsm_x4(qh[c][0], qh[c][1], qh[c][2], qh[c][3],
                    sb + r * FROWB + c * 32 + cb);
            ldsm_x4(qlr[c][0], qlr[c][1], qlr[c][2], qlr[c][3],
                    sb + 128 * FROWB + r * FROWB + c * 32 + cb);
        }
    }
    __syncthreads();   // stage0 free for K/V

    // K/V loader: tiles Kh,Kl,Vh,Vl
    auto load_kv = [&](int slot, int kt) {
        const uint32_t st = sb + slot * FSTAGE;
        const int k0 = kt * 64;
#pragma unroll
        for (int i = 0; i < 16; ++i) {
            int idx = tid + i * 256;          // < 4096
            int tile = idx >> 10;             // 0..3
            int rem = idx & 1023;
            int r = rem >> 4;
            int c = rem & 15;
            const __nv_bfloat16* src;
            if (tile == 0)      src = gk + ((size_t)(k0 + r)) * 256 +       c * 8;
            else if (tile == 1) src = gk + ((size_t)(k0 + r)) * 256 + 128 + c * 8;
            else if (tile == 2) src = gv + ((size_t)(k0 + r)) * 256 +       c * 8;
            else                src = gv + ((size_t)(k0 + r)) * 256 + 128 + c * 8;
            cp16(st + tile * FTILE + r * FROWB + c * 16, src);
        }
    };

    load_kv(0, 0); cp_commit();
    load_kv(1, 1); cp_commit();

    // per-thread softmax state + O accum
    float m_g = -INFINITY, m_g8 = -INFINITY, l_g = 0.f, l_g8 = 0.f;
    float o[16][4];
#pragma unroll
    for (int t = 0; t < 16; ++t)
#pragma unroll
        for (int q = 0; q < 4; ++q) o[t][q] = 0.f;

    const int b_row = (lane & 7) + ((lane >> 4) & 1) * 8;
    const int b_k   = ((lane >> 3) & 1) * 16;
    const int v_row = (lane & 7) + ((lane >> 3) & 1) * 8;
    const int v_cb  = ((lane >> 4) & 1) * 16;
    const int row_g = q0 + w * 16 + g;

    for (int kt = 0; kt < nkt; ++kt) {
        const int s = kt & 1;
        const int k0 = kt * 64;
        cp_wait<1>();
        __syncthreads();

        if (k0 <= q0 + w * 16 + 15) {      // warp has unmasked work
            const uint32_t sKh = sb + s * FSTAGE;
            const uint32_t sKl = sKh + FTILE;
            const uint32_t sVh = sKh + 2 * FTILE;
            const uint32_t sVl = sKh + 3 * FTILE;

            // ---- S = Qh Kh + Ql Kh + Qh Kl ----
            float s4[8][4];
#pragma unroll
            for (int j = 0; j < 8; ++j)
#pragma unroll
                for (int q = 0; q < 4; ++q) s4[j][q] = 0.f;

#pragma unroll
            for (int c8 = 0; c8 < 8; ++c8) {
                uint32_t bb[8][2];
#pragma unroll
                for (int np = 0; np < 4; ++np) {
                    uint32_t r0, r1, r2, r3;
                    ldsm_x4(r0, r1, r2, r3,
                            sKh + (np * 16 + b_row) * FROWB + c8 * 32 + b_k);
                    bb[2*np][0] = r0; bb[2*np][1] = r1;
                    bb[2*np+1][0] = r2; bb[2*np+1][1] = r3;
                }
#pragma unroll
                for (int j = 0; j < 8; ++j)
                    mma_bf16(s4[j][0], s4[j][1], s4[j][2], s4[j][3],
                             qh[c8][0], qh[c8][1], qh[c8][2], qh[c8][3],
                             bb[j][0], bb[j][1]);
#pragma unroll
                for (int j = 0; j < 8; ++j)
                    mma_bf16(s4[j][0], s4[j][1], s4[j][2], s4[j][3],
                             qlr[c8][0], qlr[c8][1], qlr[c8][2], qlr[c8][3],
                             bb[j][0], bb[j][1]);
#pragma unroll
                for (int np = 0; np < 4; ++np) {
                    uint32_t r0, r1, r2, r3;
                    ldsm_x4(r0, r1, r2, r3,
                            sKl + (np * 16 + b_row) * FROWB + c8 * 32 + b_k);
                    bb[2*np][0] = r0; bb[2*np][1] = r1;
                    bb[2*np+1][0] = r2; bb[2*np+1][1] = r3;
                }
#pragma unroll
                for (int j = 0; j < 8; ++j)
                    mma_bf16(s4[j][0], s4[j][1], s4[j][2], s4[j][3],
                             qh[c8][0], qh[c8][1], qh[c8][2], qh[c8][3],
                             bb[j][0], bb[j][1]);
            }

            // ---- scale + causal mask ----
            const bool diag = (k0 + 63 > q0 + w * 16);
#pragma unroll
            for (int j = 0; j < 8; ++j) {
                int col = k0 + j * 8 + 2 * ti;
                s4[j][0] *= scale; s4[j][1] *= scale;
                s4[j][2] *= scale; s4[j][3] *= scale;
                if (diag) {
                    if (col     > row_g)     s4[j][0] = -INFINITY;
                    if (col + 1 > row_g)     s4[j][1] = -INFINITY;
                    if (col     > row_g + 8) s4[j][2] = -INFINITY;
                    if (col + 1 > row_g + 8) s4[j][3] = -INFINITY;
                }
            }

            // ---- online softmax (per warp, quad shuffles) ----
            float tm_g = -INFINITY, tm_g8 = -INFINITY;
#pragma unroll
            for (int j = 0; j < 8; ++j) {
                tm_g  = fmaxf(tm_g,  fmaxf(s4[j][0], s4[j][1]));
                tm_g8 = fmaxf(tm_g8, fmaxf(s4[j][2], s4[j][3]));
            }
            tm_g  = fmaxf(tm_g,  __shfl_xor_sync(0xffffffffu, tm_g, 1));
            tm_g  = fmaxf(tm_g,  __shfl_xor_sync(0xffffffffu, tm_g, 2));
            tm_g8 = fmaxf(tm_g8, __shfl_xor_sync(0xffffffffu, tm_g8, 1));
            tm_g8 = fmaxf(tm_g8, __shfl_xor_sync(0xffffffffu, tm_g8, 2));

            float mn_g  = fmaxf(m_g,  tm_g);
            float mn_g8 = fmaxf(m_g8, tm_g8);
            float corr_g  = __expf(m_g  - mn_g);
            float corr_g8 = __expf(m_g8 - mn_g8);

            float sum_g = 0.f, sum_g8 = 0.f;
#pragma unroll
            for (int j = 0; j < 8; ++j) {
                s4[j][0] = __expf(s4[j][0] - mn_g);
                s4[j][1] = __expf(s4[j][1] - mn_g);
                s4[j][2] = __expf(s4[j][2] - mn_g8);
                s4[j][3] = __expf(s4[j][3] - mn_g8);
                sum_g  += s4[j][0] + s4[j][1];
                sum_g8 += s4[j][2] + s4[j][3];
            }
            sum_g  += __shfl_xor_sync(0xffffffffu, sum_g, 1);
            sum_g  += __shfl_xor_sync(0xffffffffu, sum_g, 2);
            sum_g8 += __shfl_xor_sync(0xffffffffu, sum_g8, 1);
            sum_g8 += __shfl_xor_sync(0xffffffffu, sum_g8, 2);

            l_g  = l_g  * corr_g  + sum_g;   m_g  = mn_g;
            l_g8 = l_g8 * corr_g8 + sum_g8;  m_g8 = mn_g8;

#pragma unroll
            for (int t = 0; t < 16; ++t) {
                o[t][0] *= corr_g;  o[t][1] *= corr_g;
                o[t][2] *= corr_g8; o[t][3] *= corr_g8;
            }

            // ---- O += Ph Vh + Pl Vh + Ph Vl ----
#pragma unroll
            for (int c = 0; c < 4; ++c) {
                uint32_t aPh[4], aPl[4];
                aPh[0] = pack_bf16(s4[2*c][0],   s4[2*c][1]);
                aPh[1] = pack_bf16(s4[2*c][2],   s4[2*c][3]);
                aPh[2] = pack_bf16(s4[2*c+1][0], s4[2*c+1][1]);
                aPh[3] = pack_bf16(s4[2*c+1][2], s4[2*c+1][3]);
                {
                    float2 u;
                    u = unpack_bf16(aPh[0]);
                    aPl[0] = pack_bf16(s4[2*c][0] - u.x,   s4[2*c][1] - u.y);
                    u = unpack_bf16(aPh[1]);
                    aPl[1] = pack_bf16(s4[2*c][2] - u.x,   s4[2*c][3] - u.y);
                    u = unpack_bf16(aPh[2]);
                    aPl[2] = pack_bf16(s4[2*c+1][0] - u.x, s4[2*c+1][1] - u.y);
                    u = unpack_bf16(aPh[3]);
                    aPl[3] = pack_bf16(s4[2*c+1][2] - u.x, s4[2*c+1][3] - u.y);
                }
#pragma unroll
                for (int dh = 0; dh < 2; ++dh) {
                    uint32_t bv[8][2];
#pragma unroll
                    for (int dd = 0; dd < 4; ++dd) {
                        uint32_t r0, r1, r2, r3;
                        ldsm_x4_t(r0, r1, r2, r3,
                                  sVh + (c * 16 + v_row) * FROWB
                                      + (dh * 4 + dd) * 32 + v_cb);
                        bv[2*dd][0] = r0; bv[2*dd][1] = r1;
                        bv[2*dd+1][0] = r2; bv[2*dd+1][1] = r3;
                    }
#pragma unroll
                    for (int tt = 0; tt < 8; ++tt) {
                        int t = dh * 8 + tt;
                        mma_bf16(o[t][0], o[t][1], o[t][2], o[t][3],
                                 aPh[0], aPh[1], aPh[2], aPh[3],
                                 bv[tt][0], bv[tt][1]);
                        mma_bf16(o[t][0], o[t][1], o[t][2], o[t][3],
                                 aPl[0], aPl[1], aPl[2], aPl[3],
                                 bv[tt][0], bv[tt][1]);
                    }
#pragma unroll
                    for (int dd = 0; dd < 4; ++dd) {
                        uint32_t r0, r1, r2, r3;
                        ldsm_x4_t(r0, r1, r2, r3,
                                  sVl + (c * 16 + v_row) * FROWB
                                      + (dh * 4 + dd) * 32 + v_cb);
                        bv[2*dd][0] = r0; bv[2*dd][1] = r1;
                        bv[2*dd+1][0] = r2; bv[2*dd+1][1] = r3;
                    }
#pragma unroll
                    for (int tt = 0; tt < 8; ++tt) {
                        int t = dh * 8 + tt;
                        mma_bf16(o[t][0], o[t][1], o[t][2], o[t][3],
                                 aPh[0], aPh[1], aPh[2], aPh[3],
                                 bv[tt][0], bv[tt][1]);
                    }
                }
            }
        }

        __syncthreads();
        if (kt + 2 < nkt) { load_kv(s, kt + 2); cp_commit(); }
    }

    // ---- epilogue ----
    const float inv_g  = 1.f / l_g;
    const float inv_g8 = 1.f / l_g8;
    float* og = attn + ((size_t)(b * SEQ + q0 + w * 16 + g)) * HID + h * HD;
#pragma unroll
    for (int t = 0; t < 16; ++t) {
        int d = t * 8 + 2 * ti;
        *(float2*)(og + d) = make_float2(o[t][0] * inv_g, o[t][1] * inv_g);
        *(float2*)(og + 8 * HID + d) = make_float2(o[t][2] * inv_g8, o[t][3] * inv_g8);
    }
}

// ---------------------------------------------------------------------------
// Host side
// ---------------------------------------------------------------------------
extern "C" void kernel_launch(void* const* d_in, const int* in_sizes, int n_in,
                              void* d_out, int out_size)
{
    (void)in_sizes; (void)n_in; (void)out_size;
    const float* hs      = (const float*)d_in[0];
    const float* w_qkv   = (const float*)d_in[1];
    const float* b_qkv   = (const float*)d_in[2];
    const float* w_dense = (const float*)d_in[3];
    const float* b_dense = (const float*)d_in[4];
    float* out = (float*)d_out;

    void *p_ab, *p_bqkv, *p_bdense, *p_qkv, *p_attn, *p_hs;
    cudaGetSymbolAddress(&p_ab, g_ab);
    cudaGetSymbolAddress(&p_bqkv, g_bqkv);
    cudaGetSymbolAddress(&p_bdense, g_bdense);
    cudaGetSymbolAddress(&p_qkv, g_qkv);
    cudaGetSymbolAddress(&p_attn, g_attn);
    cudaGetSymbolAddress(&p_hs, g_hsplit);

    static bool attr_done = false;
    if (!attr_done) {
        cudaFuncSetAttribute(gemm_mma_kernel,
                             cudaFuncAttributeMaxDynamicSharedMemorySize, GEMM_SMEM);
        cudaFuncSetAttribute(flash_mma_kernel,
                             cudaFuncAttributeMaxDynamicSharedMemorySize, FLASH_SMEM);
        attr_done = true;
    }

    // 1) split inputs to bf16 hi/lo
    {
        int nv = MROWS * HID / 4;
        split_kernel<<<(nv + 255) / 256, 256>>>((const float4*)hs,
                                                (__nv_bfloat162*)p_ab, nv, 0);
        nv = QKVN * HID / 4;
        split_kernel<<<(nv + 255) / 256, 256>>>((const float4*)w_qkv,
                                                (__nv_bfloat162*)p_bqkv, nv, 1);
        nv = HID * HID / 4;
        split_kernel<<<(nv + 255) / 256, 256>>>((const float4*)w_dense,
                                                (__nv_bfloat162*)p_bdense, nv, 1);
    }

    // 2) QKV projection
    {
        dim3 g(QKVN / 256, MROWS / 128);
        gemm_mma_kernel<<<g, 256, GEMM_SMEM>>>(
            (const __nv_bfloat16*)p_ab, (const __nv_bfloat16*)p_bqkv,
            b_qkv, (float*)p_qkv, QKVN);
    }

    // 3) prep per-head split, then flash attention (HMMA)
    {
        int n = MROWS * 1536;
        prep_split_kernel<<<(n + 255) / 256, 256>>>((const float4*)p_qkv,
                                                    (__nv_bfloat162*)p_hs);
        flash_mma_kernel<<<1024, 256, FLASH_SMEM>>>(
            (const __nv_bfloat16*)p_hs, (float*)p_attn);
    }

    // 4) split attention output, dense projection
    {
        int nv = MROWS * HID / 4;
        split_kernel<<<(nv + 255) / 256, 256>>>((const float4*)p_attn,
                                                (__nv_bfloat162*)p_ab, nv, 0);
        dim3 g(HID / 256, MROWS / 128);
        gemm_mma_kernel<<<g, 256, GEMM_SMEM>>>(
            (const __nv_bfloat16*)p_ab, (const __nv_bfloat16*)p_bdense,
            b_dense, out, HID);
    }
}